// round 14
// baseline (speedup 1.0000x reference)
#include <cuda_runtime.h>
#include <math.h>

#define Bb 16
#define LL 2048
#define HID 4096
#define CQ 1536
#define CKV 512
#define HH 32
#define DH 128
#define DR 64
#define HDR (HH*DR)   // 2048
#define HDH (HH*DH)   // 4096
#define L1P (LL+1)    // 2049

#define OFF_CKV (Bb*HID)
#define OFF_KR  (OFF_CKV + Bb*L1P*CKV)

// comb1 [16][4096] = [cQ(1536) | kRn(2048) | cKVn(512)]
#define C1W   4096
#define C1_KR 1536
#define C1_CKV 3584
// comb2 [16][6144] = [qC(4096) | qR(2048)]
#define C2W   6144
#define C2_QR 4096

typedef unsigned long long ull;

// ---------------- scratch ----------------
__device__ __align__(16) float g_comb1[Bb*C1W];
__device__ __align__(16) float g_comb2[Bb*C2W];
__device__ __align__(16) float g_qCeff[Bb*CKV];
__device__ __align__(16) float g_scores[Bb*L1P];
__device__ __align__(16) float g_probs [Bb*L1P];
__device__ __align__(16) float g_wsum[Bb*CKV];
__device__ __align__(16) float g_v   [Bb*HDH];

// ---------------- f32x2 helpers ----------------
__device__ __forceinline__ void fma2(ull& d, ull a, ull b) {
    asm("fma.rn.f32x2 %0, %1, %2, %0;" : "+l"(d) : "l"(a), "l"(b));
}
__device__ __forceinline__ ull pack2(float lo, float hi) {
    ull r; asm("mov.b64 %0, {%1, %2};" : "=l"(r) : "f"(lo), "f"(hi)); return r;
}
__device__ __forceinline__ void unpack2(ull v, float& lo, float& hi) {
    asm("mov.b64 {%0, %1}, %2;" : "=f"(lo), "=f"(hi) : "l"(v));
}

// ---- multi-weight split-K skinny GEMM: dst[16][Ntot] += X[16,Kslice] @ [W0|W1|W2] ----
// Epilogue: fire-and-forget atomicAdd (REDG) into pre-zeroed dst. No partials, no reduce pass.
__global__ void __launch_bounds__(128) gemm_multi(
    const float* __restrict__ X, int Xs, int K, int Kper,
    const float* __restrict__ W0, int N0,
    const float* __restrict__ W1, int N1,
    const float* __restrict__ W2, int N2,
    float* __restrict__ dst)
{
    int Ntot = N0 + N1 + N2;
    __shared__ ull sp[128*8];                 // [k][bpair], Kper <= 128
    int tid = threadIdx.x;
    int kb = blockIdx.y * Kper;

    for (int i = tid; i < Kper*8; i += 128) {
        int k = i >> 3, bp = i & 7;
        sp[i] = pack2(X[(2*bp)*Xs + kb + k], X[(2*bp+1)*Xs + kb + k]);
    }
    __syncthreads();

    int col = blockIdx.x * 512 + tid * 4;
    const float* W; int lc, Ns;
    if (col < N0)           { W = W0; lc = col;           Ns = N0; }
    else if (col < N0 + N1) { W = W1; lc = col - N0;      Ns = N1; }
    else                    { W = W2; lc = col - N0 - N1; Ns = N2; }

    ull acc[4][8];
#pragma unroll
    for (int c = 0; c < 4; c++)
#pragma unroll
        for (int p = 0; p < 8; p++) acc[c][p] = 0ull;

    const float* Wb = W + (size_t)kb * Ns + lc;
    for (int k0 = 0; k0 < Kper; k0 += 8) {
        float4 w[8];
#pragma unroll
        for (int i = 0; i < 8; i++)
            w[i] = *reinterpret_cast<const float4*>(Wb + (size_t)(k0 + i) * Ns);
#pragma unroll
        for (int i = 0; i < 8; i++) {
            ull wx = pack2(w[i].x, w[i].x), wy = pack2(w[i].y, w[i].y);
            ull wz = pack2(w[i].z, w[i].z), ww = pack2(w[i].w, w[i].w);
            const ull* xk = &sp[(k0 + i) * 8];
#pragma unroll
            for (int p = 0; p < 8; p++) {
                ull xp = xk[p];
                fma2(acc[0][p], xp, wx);
                fma2(acc[1][p], xp, wy);
                fma2(acc[2][p], xp, wz);
                fma2(acc[3][p], xp, ww);
            }
        }
    }

#pragma unroll
    for (int c = 0; c < 4; c++)
#pragma unroll
        for (int p = 0; p < 8; p++) {
            float lo, hi; unpack2(acc[c][p], lo, hi);
            atomicAdd(&dst[(size_t)(2*p)   * Ntot + col + c], lo);
            atomicAdd(&dst[(size_t)(2*p+1) * Ntot + col + c], hi);
        }
}

// ---------------- qC_eff[b,n] = dot(qC[b,:], W_UK_C[n,:]) ; 4 n per warp ----------------
__global__ void qceff_kernel(const float* __restrict__ Wukc, const float* __restrict__ comb2) {
    int b = blockIdx.y;
    int wid = threadIdx.x >> 5, lane = threadIdx.x & 31;
    __shared__ float4 sq[HDH / 4];        // 16 KB
    for (int i = threadIdx.x; i < HDH / 4; i += blockDim.x)
        sq[i] = reinterpret_cast<const float4*>(comb2 + (size_t)b * C2W)[i];
    __syncthreads();

    int n0 = blockIdx.x * 32 + wid * 4;
    const float4* w0 = reinterpret_cast<const float4*>(Wukc + (size_t)(n0+0) * HDH);
    const float4* w1 = reinterpret_cast<const float4*>(Wukc + (size_t)(n0+1) * HDH);
    const float4* w2 = reinterpret_cast<const float4*>(Wukc + (size_t)(n0+2) * HDH);
    const float4* w3 = reinterpret_cast<const float4*>(Wukc + (size_t)(n0+3) * HDH);
    float s0 = 0.f, s1 = 0.f, s2 = 0.f, s3 = 0.f;
#pragma unroll 4
    for (int j = lane; j < HDH / 4; j += 32) {
        float4 a = sq[j];
        float4 v0 = w0[j], v1 = w1[j], v2 = w2[j], v3 = w3[j];
        s0 += a.x*v0.x + a.y*v0.y + a.z*v0.z + a.w*v0.w;
        s1 += a.x*v1.x + a.y*v1.y + a.z*v1.z + a.w*v1.w;
        s2 += a.x*v2.x + a.y*v2.y + a.z*v2.z + a.w*v2.w;
        s3 += a.x*v3.x + a.y*v3.y + a.z*v3.z + a.w*v3.w;
    }
#pragma unroll
    for (int o = 16; o; o >>= 1) {
        s0 += __shfl_xor_sync(0xffffffffu, s0, o);
        s1 += __shfl_xor_sync(0xffffffffu, s1, o);
        s2 += __shfl_xor_sync(0xffffffffu, s2, o);
        s3 += __shfl_xor_sync(0xffffffffu, s3, o);
    }
    if (lane == 0) {
        g_qCeff[b * CKV + n0 + 0] = s0;
        g_qCeff[b * CKV + n0 + 1] = s1;
        g_qCeff[b * CKV + n0 + 2] = s2;
        g_qCeff[b * CKV + n0 + 3] = s3;
    }
}

// ---------------- fused: prefix scores + cache concat/copy ----------------
__global__ void score_copy(const float* __restrict__ cKV, const float* __restrict__ kRc,
                           const float* __restrict__ comb2, float* __restrict__ out)
{
    int b = blockIdx.y;
    int wid = threadIdx.x >> 5, lane = threadIdx.x & 31;
    __shared__ float4 sq[(CKV + HDR) / 4];
    for (int i = threadIdx.x; i < CKV / 4; i += blockDim.x)
        sq[i] = reinterpret_cast<const float4*>(g_qCeff + b * CKV)[i];
    for (int i = threadIdx.x; i < HDR / 4; i += blockDim.x)
        sq[CKV / 4 + i] = reinterpret_cast<const float4*>(comb2 + (size_t)b * C2W + C2_QR)[i];
    __syncthreads();

    int l = blockIdx.x * 8 + wid;
    const float4* c4  = reinterpret_cast<const float4*>(cKV + ((size_t)b * LL + l) * CKV);
    const float4* r4  = reinterpret_cast<const float4*>(kRc + ((size_t)b * LL + l) * HDR);
    float4* oc = reinterpret_cast<float4*>(out + (size_t)OFF_CKV + ((size_t)b * L1P + l) * CKV);
    float4* orr= reinterpret_cast<float4*>(out + (size_t)OFF_KR  + ((size_t)b * L1P + l) * HDR);

    float sum = 0.f;
#pragma unroll
    for (int j = 0; j < (CKV / 4) / 32; j++) {
        int idx = lane + j * 32;
        float4 v = c4[idx];                  // cached: retained in L2 for wsum
        __stcs(&oc[idx], v);
        float4 q = sq[idx];
        sum += v.x * q.x + v.y * q.y + v.z * q.z + v.w * q.w;
    }
#pragma unroll
    for (int j = 0; j < (HDR / 4) / 32; j++) {
        int idx = lane + j * 32;
        float4 v = __ldcs(&r4[idx]);         // streaming
        __stcs(&orr[idx], v);
        float4 q = sq[CKV / 4 + idx];
        sum += v.x * q.x + v.y * q.y + v.z * q.z + v.w * q.w;
    }
#pragma unroll
    for (int o = 16; o; o >>= 1) sum += __shfl_xor_sync(0xffffffffu, sum, o);
    if (lane == 0) g_scores[b * L1P + l] = sum;
}

// ---------------- fused: new-token score + new cache rows + softmax ----------------
__global__ void softmax_kernel(const float* __restrict__ comb1, float* __restrict__ out) {
    int b = blockIdx.x, tid = threadIdx.x;
    __shared__ float red[256];
    const float* cKVn = comb1 + (size_t)b * C1W + C1_CKV;
    const float* kRn  = comb1 + (size_t)b * C1W + C1_KR;

    float sum = 0.f;
    for (int i = tid; i < CKV; i += 256) {
        float v = cKVn[i];
        out[(size_t)OFF_CKV + ((size_t)b * L1P + LL) * CKV + i] = v;
        sum += v * g_qCeff[b * CKV + i];
    }
    for (int i = tid; i < HDR; i += 256) {
        float v = kRn[i];
        out[(size_t)OFF_KR + ((size_t)b * L1P + LL) * HDR + i] = v;
        sum += v * g_comb2[(size_t)b * C2W + C2_QR + i];
    }
    red[tid] = sum; __syncthreads();
    for (int s = 128; s; s >>= 1) { if (tid < s) red[tid] += red[tid + s]; __syncthreads(); }
    if (tid == 0) g_scores[b * L1P + LL] = red[0];
    __syncthreads();

    const float scale = rsqrtf((float)(DH + DR));
    float m = -1e30f;
    for (int i = tid; i < L1P; i += 256) m = fmaxf(m, g_scores[b * L1P + i] * scale);
    red[tid] = m; __syncthreads();
    for (int s = 128; s; s >>= 1) { if (tid < s) red[tid] = fmaxf(red[tid], red[tid + s]); __syncthreads(); }
    m = red[0]; __syncthreads();
    float esum = 0.f;
    for (int i = tid; i < L1P; i += 256) {
        float e = expf(g_scores[b * L1P + i] * scale - m);
        g_probs[b * L1P + i] = e;
        esum += e;
    }
    red[tid] = esum; __syncthreads();
    for (int s = 128; s; s >>= 1) { if (tid < s) red[tid] += red[tid + s]; __syncthreads(); }
    float inv = 1.f / red[0];
    __syncthreads();
    for (int i = tid; i < L1P; i += 256) g_probs[b * L1P + i] *= inv;
}

// ---------------- probs-weighted cKV sum -> atomic into g_wsum ----------------
__global__ void wsum_kernel(const float* __restrict__ cKV, const float* __restrict__ comb1) {
    int b = blockIdx.x, ls = blockIdx.y, tid = threadIdx.x;
    const float4* c4 = reinterpret_cast<const float4*>(cKV + (size_t)b * LL * CKV);
    float4 acc = make_float4(0.f, 0.f, 0.f, 0.f);
    int l0 = ls * (LL / 32);
#pragma unroll 8
    for (int l = l0; l < l0 + LL / 32; l++) {
        float p = g_probs[b * L1P + l];
        float4 v = c4[(size_t)l * (CKV / 4) + tid];
        acc.x = fmaf(p, v.x, acc.x); acc.y = fmaf(p, v.y, acc.y);
        acc.z = fmaf(p, v.z, acc.z); acc.w = fmaf(p, v.w, acc.w);
    }
    if (ls == 0) {
        float p = g_probs[b * L1P + LL];
        float4 v = *reinterpret_cast<const float4*>(comb1 + (size_t)b * C1W + C1_CKV + tid * 4);
        acc.x = fmaf(p, v.x, acc.x); acc.y = fmaf(p, v.y, acc.y);
        acc.z = fmaf(p, v.z, acc.z); acc.w = fmaf(p, v.w, acc.w);
    }
    atomicAdd(&g_wsum[b * CKV + tid * 4 + 0], acc.x);
    atomicAdd(&g_wsum[b * CKV + tid * 4 + 1], acc.y);
    atomicAdd(&g_wsum[b * CKV + tid * 4 + 2], acc.z);
    atomicAdd(&g_wsum[b * CKV + tid * 4 + 3], acc.w);
}

// ---------------- launch ----------------
extern "C" void kernel_launch(void* const* d_in, const int* in_sizes, int n_in,
                              void* d_out, int out_size) {
    const float* h     = (const float*)d_in[0];
    const float* cKV   = (const float*)d_in[1];
    const float* kRc   = (const float*)d_in[2];
    const float* W_DQ  = (const float*)d_in[3];
    const float* W_DKV = (const float*)d_in[4];
    const float* W_UQC = (const float*)d_in[5];
    const float* W_UQR = (const float*)d_in[6];
    const float* W_KR  = (const float*)d_in[7];
    const float* W_UKC = (const float*)d_in[8];
    const float* W_UVC = (const float*)d_in[9];
    const float* W_O   = (const float*)d_in[10];
    float* out = (float*)d_out;

    float *p_c1, *p_c2, *p_wsum, *p_v;
    cudaGetSymbolAddress((void**)&p_c1,   g_comb1);
    cudaGetSymbolAddress((void**)&p_c2,   g_comb2);
    cudaGetSymbolAddress((void**)&p_wsum, g_wsum);
    cudaGetSymbolAddress((void**)&p_v,    g_v);

    // zero all atomic destinations (tiny, ~0.5 MB total)
    cudaMemsetAsync(p_c1,   0, Bb*C1W*sizeof(float));
    cudaMemsetAsync(p_c2,   0, Bb*C2W*sizeof(float));
    cudaMemsetAsync(p_wsum, 0, Bb*CKV*sizeof(float));
    cudaMemsetAsync(p_v,    0, Bb*HDH*sizeof(float));
    cudaMemsetAsync(out,    0, Bb*HID*sizeof(float));

    // proj1: h @ [W_DQ | W_KR | W_DKV] -> comb1  (K=4096, dup=64, Kper=64)
    gemm_multi<<<dim3(8, 64), 128>>>(h, HID, 4096, 64,
                                     W_DQ, 1536, W_KR, 2048, W_DKV, 512, p_c1);

    // proj2: cQ @ [W_UQ_C | W_UQ_R] -> comb2  (K=1536, dup=32, Kper=48)
    gemm_multi<<<dim3(12, 32), 128>>>(p_c1, C1W, 1536, 48,
                                      W_UQC, 4096, W_UQR, 2048, (const float*)0, 0, p_c2);

    // qC_eff = qC @ W_UK_C^T  (4 n per warp)
    qceff_kernel<<<dim3(16, 16), 256>>>(W_UKC, p_c2);

    // prefix scores + cache copy (HBM-heavy)
    score_copy<<<dim3(256, 16), 256>>>(cKV, kRc, p_c2, out);

    // new-token score + new cache rows + softmax
    softmax_kernel<<<16, 256>>>(p_c1, out);

    // probs-weighted cKV -> g_wsum (atomic)
    wsum_kernel<<<dim3(16, 32), 128>>>(cKV, p_c1);

    // v = wsum @ W_UV_C  (K=512, dup=32, Kper=16)
    gemm_multi<<<dim3(8, 32), 128>>>(p_wsum, CKV, 512, 16,
                                     W_UVC, 4096, (const float*)0, 0, (const float*)0, 0, p_v);

    // out = v @ W_O  (K=4096, dup=32, Kper=128)
    gemm_multi<<<dim3(8, 32), 128>>>(p_v, HDH, 4096, 128,
                                     W_O, 4096, (const float*)0, 0, (const float*)0, 0, out);
}